// round 2
// baseline (speedup 1.0000x reference)
#include <cuda_runtime.h>

// Problem constants
#define NB 2
#define NS 2048
#define ND 1024
#define NH 16
#define HD 64
#define NM (NB * NS)          // 4096 rows in projection GEMMs

// Scratch: Q/K/V in head layout [B*H][S][HD]  (16.8 MB each, static device arrays)
__device__ float g_q[NB * NH * NS * HD];
__device__ float g_k[NB * NH * NS * HD];
__device__ float g_v[NB * NH * NS * HD];

// Fast exp via FMA-pipe polynomial (avoids MUFU bottleneck: 134M exps would cost ~1ms).
// exp(x) = 2^(x*log2e); degree-5 poly for 2^f on [0,1); max rel err ~1.5e-4.
__device__ __forceinline__ float fexp(float x) {
    x = fmaxf(x, -60.0f);
    float t = x * 1.4426950408889634f;
    float fn = floorf(t);
    float f = t - fn;
    float r = 1.3333558e-3f;
    r = fmaf(r, f, 9.6181291e-3f);
    r = fmaf(r, f, 5.5504109e-2f);
    r = fmaf(r, f, 2.4022651e-1f);
    r = fmaf(r, f, 6.9314718e-1f);
    r = fmaf(r, f, 1.0f);
    int e = (int)fn;
    return __int_as_float((e + 127) << 23) * r;
}

// ---------------------------------------------------------------------------
// Projection SGEMM: dst = X[4096,1024] * W[1024,1024] + bias, written directly
// in head layout [B*H][S][HD]. blockIdx.z selects q/k/v.
// Tile 128x128x16, 256 threads, 8x8 microtile (split 4+4 to keep smem reads
// conflict-free / float4-aligned).
// ---------------------------------------------------------------------------
__global__ __launch_bounds__(256, 2)
void proj_kernel(const float* __restrict__ xq, const float* __restrict__ xk,
                 const float* __restrict__ xv,
                 const float* __restrict__ wq, const float* __restrict__ bq,
                 const float* __restrict__ wk, const float* __restrict__ bk,
                 const float* __restrict__ wv, const float* __restrict__ bv) {
    __shared__ float As[16][132];   // A transposed: As[k][m], padded stride
    __shared__ float Bs[16][128];   // Bs[k][n]

    const int z = blockIdx.z;
    const float* X    = (z == 0) ? xq : (z == 1) ? xk : xv;
    const float* W    = (z == 0) ? wq : (z == 1) ? wk : wv;
    const float* bias = (z == 0) ? bq : (z == 1) ? bk : bv;
    float* dst        = (z == 0) ? g_q : (z == 1) ? g_k : g_v;

    const int tid = threadIdx.x;
    const int tx = tid & 15;
    const int ty = tid >> 4;
    const int m0 = blockIdx.y * 128;
    const int n0 = blockIdx.x * 128;

    float acc[8][8];
#pragma unroll
    for (int i = 0; i < 8; i++)
#pragma unroll
        for (int j = 0; j < 8; j++) acc[i][j] = 0.f;

    for (int k0 = 0; k0 < ND; k0 += 16) {
#pragma unroll
        for (int q = 0; q < 2; q++) {
            int idx = tid + q * 256;
            // A tile 128x16, transpose into As[k][m]
            int ar = idx >> 2;
            int ac = (idx & 3) << 2;
            float4 va = *(const float4*)(X + (m0 + ar) * ND + k0 + ac);
            As[ac + 0][ar] = va.x;
            As[ac + 1][ar] = va.y;
            As[ac + 2][ar] = va.z;
            As[ac + 3][ar] = va.w;
            // B tile 16x128
            int br = idx >> 5;
            int bc = (idx & 31) << 2;
            *(float4*)&Bs[br][bc] = *(const float4*)(W + (k0 + br) * ND + n0 + bc);
        }
        __syncthreads();
#pragma unroll
        for (int k = 0; k < 16; k++) {
            float a[8], b[8];
            *(float4*)&a[0] = *(const float4*)&As[k][ty * 4];
            *(float4*)&a[4] = *(const float4*)&As[k][64 + ty * 4];
            *(float4*)&b[0] = *(const float4*)&Bs[k][tx * 4];
            *(float4*)&b[4] = *(const float4*)&Bs[k][64 + tx * 4];
#pragma unroll
            for (int i = 0; i < 8; i++)
#pragma unroll
                for (int j = 0; j < 8; j++)
                    acc[i][j] = fmaf(a[i], b[j], acc[i][j]);
        }
        __syncthreads();
    }

    // Epilogue: bias add + store in head layout. A 4-aligned 4-wide column
    // chunk never crosses a 64-wide head boundary.
    float bia[8];
    *(float4*)&bia[0] = *(const float4*)(bias + n0 + tx * 4);
    *(float4*)&bia[4] = *(const float4*)(bias + n0 + 64 + tx * 4);

#pragma unroll
    for (int i = 0; i < 8; i++) {
        int m = m0 + ((i < 4) ? (ty * 4 + i) : (64 + ty * 4 + (i - 4)));
        int bb = m >> 11;          // / NS
        int s  = m & (NS - 1);
#pragma unroll
        for (int half = 0; half < 2; half++) {
            int n  = n0 + half * 64 + tx * 4;
            int h  = n >> 6;
            int hd = n & 63;
            float4 vo;
            vo.x = acc[i][half * 4 + 0] + bia[half * 4 + 0];
            vo.y = acc[i][half * 4 + 1] + bia[half * 4 + 1];
            vo.z = acc[i][half * 4 + 2] + bia[half * 4 + 2];
            vo.w = acc[i][half * 4 + 3] + bia[half * 4 + 3];
            *(float4*)(dst + ((bb * NH + h) * NS + s) * HD + hd) = vo;
        }
    }
}

// ---------------------------------------------------------------------------
// Flash attention: per CTA one (b,h) pair and one 64-row Q tile; iterate over
// 32 K/V tiles of 64 with online softmax. 256 threads (16x16), 4x4 microtile.
// Q/K stored transposed (stride 68: 16B-aligned rows for LDS.128), V natural,
// P at stride 65 (scalar access).
// ---------------------------------------------------------------------------
#define AQ 68
#define AP 65
#define ATT_SMEM ((3 * 64 * AQ + 64 * AP) * 4)

__global__ __launch_bounds__(256, 2)
void attn_kernel(float* __restrict__ out) {
    extern __shared__ float sm[];
    float* Qs = sm;                 // Qs[d][r]
    float* Ks = sm + 64 * AQ;       // Ks[d][c]
    float* Vs = sm + 2 * 64 * AQ;   // Vs[j][c]
    float* Ps = sm + 3 * 64 * AQ;   // Ps[j][r]

    const int tid = threadIdx.x;
    const int tx = tid & 15;
    const int ty = tid >> 4;
    const int qt = blockIdx.x;      // 0..31 Q tile
    const int bh = blockIdx.y;      // 0..31 (b*H + h)

    const float* Qg = g_q + bh * NS * HD + qt * 64 * HD;
    const float* Kg = g_k + bh * NS * HD;
    const float* Vg = g_v + bh * NS * HD;

    // Load Q tile transposed: Qs[d][r]
    {
        int rr = tid >> 4;
        int d0 = (tid & 15) << 2;
#pragma unroll
        for (int q = 0; q < 4; q++) {
            int r = rr + q * 16;
            float4 v = *(const float4*)(Qg + r * HD + d0);
            Qs[(d0 + 0) * AQ + r] = v.x;
            Qs[(d0 + 1) * AQ + r] = v.y;
            Qs[(d0 + 2) * AQ + r] = v.z;
            Qs[(d0 + 3) * AQ + r] = v.w;
        }
    }

    float m_i[4], l_i[4], o[4][4];
#pragma unroll
    for (int i = 0; i < 4; i++) {
        m_i[i] = -1e30f;
        l_i[i] = 0.f;
#pragma unroll
        for (int c = 0; c < 4; c++) o[i][c] = 0.f;
    }

    for (int kt = 0; kt < NS / 64; kt++) {
        __syncthreads();  // protects Ks/Vs/Ps against previous iteration (and Q load, iter 0)
        {
            int rr = tid >> 4;
            int d0 = (tid & 15) << 2;
#pragma unroll
            for (int q = 0; q < 4; q++) {
                int r = rr + q * 16;
                float4 kv = *(const float4*)(Kg + (kt * 64 + r) * HD + d0);
                Ks[(d0 + 0) * AQ + r] = kv.x;
                Ks[(d0 + 1) * AQ + r] = kv.y;
                Ks[(d0 + 2) * AQ + r] = kv.z;
                Ks[(d0 + 3) * AQ + r] = kv.w;
                float4 vv = *(const float4*)(Vg + (kt * 64 + r) * HD + d0);
                *(float4*)&Vs[r * AQ + d0] = vv;
            }
        }
        __syncthreads();

        // GEMM1: S = Q * K^T  (thread owns rows ty*4.., cols tx*4..)
        float sacc[4][4];
#pragma unroll
        for (int i = 0; i < 4; i++)
#pragma unroll
            for (int j = 0; j < 4; j++) sacc[i][j] = 0.f;

#pragma unroll 8
        for (int d = 0; d < 64; d++) {
            float4 qa4 = *(const float4*)&Qs[d * AQ + ty * 4];
            float4 kb4 = *(const float4*)&Ks[d * AQ + tx * 4];
            float qa[4] = {qa4.x, qa4.y, qa4.z, qa4.w};
            float kb[4] = {kb4.x, kb4.y, kb4.z, kb4.w};
#pragma unroll
            for (int i = 0; i < 4; i++)
#pragma unroll
                for (int j = 0; j < 4; j++)
                    sacc[i][j] = fmaf(qa[i], kb[j], sacc[i][j]);
        }

        // Online softmax per row (row spread across 16 lanes; xor-shuffles
        // with offsets <16 stay inside the row group).
#pragma unroll
        for (int i = 0; i < 4; i++) {
            float t0 = sacc[i][0] * 0.125f;
            float t1 = sacc[i][1] * 0.125f;
            float t2 = sacc[i][2] * 0.125f;
            float t3 = sacc[i][3] * 0.125f;
            float mx = fmaxf(fmaxf(t0, t1), fmaxf(t2, t3));
            mx = fmaxf(mx, __shfl_xor_sync(0xffffffffu, mx, 1));
            mx = fmaxf(mx, __shfl_xor_sync(0xffffffffu, mx, 2));
            mx = fmaxf(mx, __shfl_xor_sync(0xffffffffu, mx, 4));
            mx = fmaxf(mx, __shfl_xor_sync(0xffffffffu, mx, 8));
            float newm = fmaxf(m_i[i], mx);
            float corr = fexp(m_i[i] - newm);
            m_i[i] = newm;
            l_i[i] *= corr;
            o[i][0] *= corr; o[i][1] *= corr; o[i][2] *= corr; o[i][3] *= corr;
            float p0 = fexp(t0 - newm);
            float p1 = fexp(t1 - newm);
            float p2 = fexp(t2 - newm);
            float p3 = fexp(t3 - newm);
            int r = ty * 4 + i;
            Ps[(tx * 4 + 0) * AP + r] = p0;
            Ps[(tx * 4 + 1) * AP + r] = p1;
            Ps[(tx * 4 + 2) * AP + r] = p2;
            Ps[(tx * 4 + 3) * AP + r] = p3;
            float rs = (p0 + p1) + (p2 + p3);
            rs += __shfl_xor_sync(0xffffffffu, rs, 1);
            rs += __shfl_xor_sync(0xffffffffu, rs, 2);
            rs += __shfl_xor_sync(0xffffffffu, rs, 4);
            rs += __shfl_xor_sync(0xffffffffu, rs, 8);
            l_i[i] += rs;
        }
        __syncthreads();  // P visible to all before GEMM2

        // GEMM2: O += P * V
#pragma unroll 8
        for (int j = 0; j < 64; j++) {
            float4 vb4 = *(const float4*)&Vs[j * AQ + tx * 4];
            float vb[4] = {vb4.x, vb4.y, vb4.z, vb4.w};
            float pr[4];
#pragma unroll
            for (int i = 0; i < 4; i++) pr[i] = Ps[j * AP + ty * 4 + i];
#pragma unroll
            for (int i = 0; i < 4; i++)
#pragma unroll
                for (int c = 0; c < 4; c++)
                    o[i][c] = fmaf(pr[i], vb[c], o[i][c]);
        }
    }

    // Epilogue: normalize and write [B,S,D]
    const int b = bh >> 4;
    const int h = bh & 15;
#pragma unroll
    for (int i = 0; i < 4; i++) {
        int s = qt * 64 + ty * 4 + i;
        float inv = 1.0f / l_i[i];
        float4 vo;
        vo.x = o[i][0] * inv;
        vo.y = o[i][1] * inv;
        vo.z = o[i][2] * inv;
        vo.w = o[i][3] * inv;
        *(float4*)(out + (b * NS + s) * ND + h * HD + tx * 4) = vo;
    }
}

// ---------------------------------------------------------------------------
extern "C" void kernel_launch(void* const* d_in, const int* in_sizes, int n_in,
                              void* d_out, int out_size) {
    const float* query = (const float*)d_in[0];
    const float* key_  = (const float*)d_in[1];
    const float* value = (const float*)d_in[2];
    const float* Wq    = (const float*)d_in[3];
    const float* bq    = (const float*)d_in[4];
    const float* Wk    = (const float*)d_in[5];
    const float* bk    = (const float*)d_in[6];
    const float* Wv    = (const float*)d_in[7];
    const float* bv    = (const float*)d_in[8];
    float* out = (float*)d_out;

    cudaFuncSetAttribute(attn_kernel, cudaFuncAttributeMaxDynamicSharedMemorySize,
                         ATT_SMEM);

    dim3 pg(ND / 128, NM / 128, 3);
    proj_kernel<<<pg, 256>>>(query, key_, value, Wq, bq, Wk, bk, Wv, bv);

    dim3 ag(NS / 64, NB * NH);
    attn_kernel<<<ag, 256, ATT_SMEM>>>(out);
}